// round 4
// baseline (speedup 1.0000x reference)
#include <cuda_runtime.h>
#include <math.h>

#define BATCH 2
#define NPTS 4096
#define MPTS 4096
#define NSTEPS 8
#define TOLER 1e-6f

#define TPB 256
#define MSPLIT 32
#define MCH (MPTS / MSPLIT)        // 128 targets per tile
#define SRCB (TPB * 2)             // 512 source points per block (2/thread)
#define NCHUNK (NPTS / SRCB)       // 8 source chunks
#define GRID_BLKS (BATCH * NCHUNK * MSPLIT)   // 512 blocks

// ---------------- device state ----------------
__device__ float4 g_tgt4[BATCH * MPTS];             // (x,y,z,|t|^2)
__device__ unsigned long long g_scr[BATCH * NPTS];  // packed (orderable score | idx)
__device__ float g_Rcum[BATCH][9];
__device__ float g_tcum[BATCH][3];
__device__ float g_err[BATCH];
__device__ int g_done;
__device__ unsigned g_count;

// ---------------- init ----------------
__global__ void init_kernel(const float* __restrict__ ptgt) {
    int i = blockIdx.x * blockDim.x + threadIdx.x;  // 0..8191
    if (i < BATCH * MPTS) {
        float x = ptgt[i * 3 + 0];
        float y = ptgt[i * 3 + 1];
        float z = ptgt[i * 3 + 2];
        g_tgt4[i] = make_float4(x, y, z, x * x + y * y + z * z);
        g_scr[i] = 0xFFFFFFFFFFFFFFFFull;
    }
    if (i == 0) { g_done = 0; g_count = 0; }
    if (i < BATCH) {
        g_err[i] = 0.0f;
        float* R = g_Rcum[i];
        R[0] = 1.f; R[1] = 0.f; R[2] = 0.f;
        R[3] = 0.f; R[4] = 1.f; R[5] = 0.f;
        R[6] = 0.f; R[7] = 0.f; R[8] = 1.f;
        g_tcum[i][0] = 0.f; g_tcum[i][1] = 0.f; g_tcum[i][2] = 0.f;
    }
}

// ---------------- Horn quaternion Kabsch helpers ----------------
__device__ __forceinline__ void matmul4(float* C, const float* A, const float* Bm) {
#pragma unroll
    for (int i = 0; i < 4; i++)
#pragma unroll
        for (int j = 0; j < 4; j++) {
            float a = 0.f;
#pragma unroll
            for (int k = 0; k < 4; k++) a = __fmaf_rn(A[i * 4 + k], Bm[k * 4 + j], a);
            C[i * 4 + j] = a;
        }
}

__device__ void solve_horn(const double* S, double* Rn, double* tn) {
    const double n = (double)NPTS;
    const double inv = 1.0 / n;
    const double pmx = S[0] * inv, pmy = S[1] * inv, pmz = S[2] * inv;
    const double qmx = S[3] * inv, qmy = S[4] * inv, qmz = S[5] * inv;

    const double Sxx = S[6]  - n * pmx * qmx, Sxy = S[7]  - n * pmx * qmy, Sxz = S[8]  - n * pmx * qmz;
    const double Syx = S[9]  - n * pmy * qmx, Syy = S[10] - n * pmy * qmy, Syz = S[11] - n * pmy * qmz;
    const double Szx = S[12] - n * pmz * qmx, Szy = S[13] - n * pmz * qmy, Szz = S[14] - n * pmz * qmz;

    double K[16];
    K[0]  = Sxx + Syy + Szz; K[1]  = Syz - Szy;       K[2]  = Szx - Sxz;       K[3]  = Sxy - Syx;
    K[5]  = Sxx - Syy - Szz; K[6]  = Sxy + Syx;       K[7]  = Szx + Sxz;
    K[10] = -Sxx + Syy - Szz; K[11] = Syz + Szy;
    K[15] = -Sxx - Syy + Szz;
    K[4] = K[1]; K[8] = K[2]; K[12] = K[3]; K[9] = K[6]; K[13] = K[7]; K[14] = K[11];

    double fro = 0.0;
#pragma unroll
    for (int i = 0; i < 16; i++) fro += K[i] * K[i];
    const double sc = 1.0 / sqrt(fro + 1e-300);

    float Kf[16];
#pragma unroll
    for (int i = 0; i < 16; i++) Kf[i] = (float)(K[i] * sc);
    Kf[0] += 1.f; Kf[5] += 1.f; Kf[10] += 1.f; Kf[15] += 1.f;  // eigs in [0,2]

    float K2[16], K4[16];
    matmul4(K2, Kf, Kf);
    matmul4(K4, K2, K2);

    float v0 = 1.f, v1 = 0.02f, v2 = 0.03f, v3 = 0.04f;
#pragma unroll 4
    for (int it = 0; it < 48; it++) {
        float w0 = K4[0]  * v0 + K4[1]  * v1 + K4[2]  * v2 + K4[3]  * v3;
        float w1 = K4[4]  * v0 + K4[5]  * v1 + K4[6]  * v2 + K4[7]  * v3;
        float w2 = K4[8]  * v0 + K4[9]  * v1 + K4[10] * v2 + K4[11] * v3;
        float w3 = K4[12] * v0 + K4[13] * v1 + K4[14] * v2 + K4[15] * v3;
        if ((it & 3) == 3) {
            float r = rsqrtf(w0 * w0 + w1 * w1 + w2 * w2 + w3 * w3 + 1e-30f);
            w0 *= r; w1 *= r; w2 *= r; w3 *= r;
        }
        v0 = w0; v1 = w1; v2 = w2; v3 = w3;
    }

    const double qw = v0, qx = v1, qy = v2, qz = v3;
    const double nn = qw * qw + qx * qx + qy * qy + qz * qz;
    const double s2 = 2.0 / nn;
    Rn[0] = 1.0 - s2 * (qy * qy + qz * qz); Rn[1] = s2 * (qx * qy - qw * qz); Rn[2] = s2 * (qx * qz + qw * qy);
    Rn[3] = s2 * (qx * qy + qw * qz); Rn[4] = 1.0 - s2 * (qx * qx + qz * qz); Rn[5] = s2 * (qy * qz - qw * qx);
    Rn[6] = s2 * (qx * qz - qw * qy); Rn[7] = s2 * (qy * qz + qw * qx); Rn[8] = 1.0 - s2 * (qx * qx + qy * qy);

    tn[0] = qmx - (Rn[0] * pmx + Rn[1] * pmy + Rn[2] * pmz);
    tn[1] = qmy - (Rn[3] * pmx + Rn[4] * pmy + Rn[5] * pmz);
    tn[2] = qmz - (Rn[6] * pmx + Rn[7] * pmy + Rn[8] * pmz);
}

// ---------------- critical tail (single last block, 256 threads) ----------------
__device__ void critical_tail(const float* __restrict__ psrc, float* __restrict__ out,
                              int step, int done0) {
    __shared__ float cRt[BATCH][12];
    __shared__ float c_part[8][16];
    __shared__ float c_S[BATCH][16];
    __shared__ float c_errnew[BATCH];
    __shared__ int c_done;

    const int tid = threadIdx.x;

    if (tid < 24) {
        int bb = tid / 12, j = tid - bb * 12;
        cRt[bb][j] = (j < 9) ? g_Rcum[bb][j] : g_tcum[bb][j - 9];
    }
    __syncthreads();

    float acc[16];
#pragma unroll
    for (int k = 0; k < 16; k++) acc[k] = 0.f;

    const int base = tid * 32;   // 32 contiguous points, all in batch tid>>7
    const int bb = tid >> 7;

    if (!done0) {
        const float R0 = cRt[bb][0], R1 = cRt[bb][1], R2 = cRt[bb][2];
        const float R3 = cRt[bb][3], R4 = cRt[bb][4], R5 = cRt[bb][5];
        const float R6 = cRt[bb][6], R7 = cRt[bb][7], R8 = cRt[bb][8];
        const float t0 = cRt[bb][9], t1 = cRt[bb][10], t2 = cRt[bb][11];

        for (int c = 0; c < 32; c += 8) {
            unsigned long long key[8];
#pragma unroll
            for (int i = 0; i < 8; i++) key[i] = __ldcg(&g_scr[base + c + i]);
#pragma unroll
            for (int i = 0; i < 8; i++) __stcg(&g_scr[base + c + i], 0xFFFFFFFFFFFFFFFFull);

            float4 q[8];
#pragma unroll
            for (int i = 0; i < 8; i++) {
                const int idx = ((int)(unsigned)(key[i] & 0xFFFFFFFFull)) & (MPTS - 1);
                q[i] = g_tgt4[(bb << 12) + idx];
            }
#pragma unroll
            for (int i = 0; i < 8; i++) {
                unsigned u = (unsigned)(key[i] >> 32);
                unsigned fb = (u & 0x80000000u) ? (u ^ 0x80000000u) : ~u;
                const float s = __uint_as_float(fb);

                const float* ps = psrc + (size_t)(base + c + i) * 3;
                const float x = ps[0], y = ps[1], z = ps[2];
                const float px = R0 * x + R1 * y + R2 * z + t0;
                const float py = R3 * x + R4 * y + R5 * z + t1;
                const float pz = R6 * x + R7 * y + R8 * z + t2;
                const float pn = px * px + py * py + pz * pz;
                const float dist = sqrtf(fmaxf(pn + s, 0.0f));

                acc[0] += px; acc[1] += py; acc[2] += pz;
                acc[3] += q[i].x; acc[4] += q[i].y; acc[5] += q[i].z;
                acc[6] += px * q[i].x; acc[7] += px * q[i].y; acc[8] += px * q[i].z;
                acc[9] += py * q[i].x; acc[10] += py * q[i].y; acc[11] += py * q[i].z;
                acc[12] += pz * q[i].x; acc[13] += pz * q[i].y; acc[14] += pz * q[i].z;
                acc[15] += dist;
            }
        }
    } else {
        for (int i = 0; i < 32; i++) __stcg(&g_scr[base + i], 0xFFFFFFFFFFFFFFFFull);
    }

    // fixed-order deterministic reduction
#pragma unroll
    for (int k = 0; k < 16; k++) {
        float a = acc[k];
        a += __shfl_down_sync(0xffffffffu, a, 16);
        a += __shfl_down_sync(0xffffffffu, a, 8);
        a += __shfl_down_sync(0xffffffffu, a, 4);
        a += __shfl_down_sync(0xffffffffu, a, 2);
        a += __shfl_down_sync(0xffffffffu, a, 1);
        acc[k] = a;
    }
    const int lane = tid & 31, warp = tid >> 5;   // warps 0-3 batch0, 4-7 batch1
    if (lane == 0) {
#pragma unroll
        for (int k = 0; k < 16; k++) c_part[warp][k] = acc[k];
    }
    __syncthreads();
    if (tid < 32) {
        const int bsel = tid >> 4, k = tid & 15;
        float a = 0.f;
#pragma unroll
        for (int w = 0; w < 4; w++) a += c_part[bsel * 4 + w][k];
        c_S[bsel][k] = a;
        if (k == 15) c_errnew[bsel] = a / (float)NPTS;
    }
    __syncthreads();

    if (tid == 0) {
        int conv = (fabsf(c_errnew[0] - g_err[0]) < TOLER) &&
                   (fabsf(c_errnew[1] - g_err[1]) < TOLER);
        c_done = (done0 || conv) ? 1 : 0;
        g_done = c_done;
        g_count = 0;                 // re-arm completion counter for next step
    }
    __syncthreads();

    if (tid < BATCH && !c_done) {
        double S[16];
#pragma unroll
        for (int k = 0; k < 16; k++) S[k] = (double)c_S[tid][k];
        double Rn[9], tn[3];
        solve_horn(S, Rn, tn);

        double Ro[9], to[3];
#pragma unroll
        for (int i = 0; i < 9; i++) Ro[i] = (double)cRt[tid][i];
#pragma unroll
        for (int i = 0; i < 3; i++) to[i] = (double)cRt[tid][9 + i];

#pragma unroll
        for (int i = 0; i < 3; i++) {
#pragma unroll
            for (int j = 0; j < 3; j++) {
                double m = Rn[i * 3 + 0] * Ro[0 + j] + Rn[i * 3 + 1] * Ro[3 + j] +
                           Rn[i * 3 + 2] * Ro[6 + j];
                g_Rcum[tid][i * 3 + j] = (float)m;
            }
            double tm = Rn[i * 3 + 0] * to[0] + Rn[i * 3 + 1] * to[1] +
                        Rn[i * 3 + 2] * to[2] + tn[i];
            g_tcum[tid][i] = (float)tm;
        }
        g_err[tid] = c_errnew[tid];
    }
    __syncthreads();

    if (step == NSTEPS - 1 && tid < BATCH) {
        float R[9];
#pragma unroll
        for (int i = 0; i < 9; i++) R[i] = g_Rcum[tid][i];
        out[tid * 7 + 0] = g_tcum[tid][0];
        out[tid * 7 + 1] = g_tcum[tid][1];
        out[tid * 7 + 2] = g_tcum[tid][2];
        const float r00 = R[0], r11 = R[4], r22 = R[8];
        float qw = 0.5f * sqrtf(fmaxf(1.f + r00 + r11 + r22, 1e-12f));
        float qx = 0.5f * sqrtf(fmaxf(1.f + r00 - r11 - r22, 1e-12f));
        float qy = 0.5f * sqrtf(fmaxf(1.f - r00 + r11 - r22, 1e-12f));
        float qz = 0.5f * sqrtf(fmaxf(1.f - r00 - r11 + r22, 1e-12f));
        qx = (R[7] - R[5] >= 0.f) ? qx : -qx;
        qy = (R[2] - R[6] >= 0.f) ? qy : -qy;
        qz = (R[3] - R[1] >= 0.f) ? qz : -qz;
        out[tid * 7 + 3] = qx;
        out[tid * 7 + 4] = qy;
        out[tid * 7 + 5] = qz;
        out[tid * 7 + 6] = qw;
    }
}

// ---------------- one ICP step: NN + (last block) reduce/solve ----------------
__global__ __launch_bounds__(TPB, 4) void nn_step_kernel(const float* __restrict__ psrc,
                                                         float* __restrict__ out,
                                                         int step) {
    __shared__ float4 sh[MCH];
    __shared__ float sRt[12];
    __shared__ int s_last;

    const int tid = threadIdx.x;
    const int bx = blockIdx.x;
    const int mtile = bx & (MSPLIT - 1);
    const int nchunk = (bx >> 5) & (NCHUNK - 1);
    const int b = bx >> 8;
    const int mbase = mtile * MCH;
    const int nbase = nchunk * SRCB;

    const int done0 = g_done;

    if (!done0) {
        if (tid < MCH) sh[tid] = g_tgt4[b * MPTS + mbase + tid];
        if (tid < 12)
            sRt[tid] = (tid < 9) ? g_Rcum[b][tid] : g_tcum[b][tid - 9];
        __syncthreads();

        const float R0 = sRt[0], R1 = sRt[1], R2 = sRt[2];
        const float R3 = sRt[3], R4 = sRt[4], R5 = sRt[5];
        const float R6 = sRt[6], R7 = sRt[7], R8 = sRt[8];
        const float t0 = sRt[9], t1 = sRt[10], t2 = sRt[11];

        const int n0 = nbase + tid;
        const int n1 = nbase + tid + TPB;
        const float* p0 = psrc + ((size_t)b * NPTS + n0) * 3;
        const float* p1 = psrc + ((size_t)b * NPTS + n1) * 3;
        const float x0 = p0[0], y0 = p0[1], z0 = p0[2];
        const float x1 = p1[0], y1 = p1[1], z1 = p1[2];

        const float px0 = R0 * x0 + R1 * y0 + R2 * z0 + t0;
        const float py0 = R3 * x0 + R4 * y0 + R5 * z0 + t1;
        const float pz0 = R6 * x0 + R7 * y0 + R8 * z0 + t2;
        const float px1 = R0 * x1 + R1 * y1 + R2 * z1 + t0;
        const float py1 = R3 * x1 + R4 * y1 + R5 * z1 + t1;
        const float pz1 = R6 * x1 + R7 * y1 + R8 * z1 + t2;
        const float ax0 = -2.f * px0, ay0 = -2.f * py0, az0 = -2.f * pz0;
        const float ax1 = -2.f * px1, ay1 = -2.f * py1, az1 = -2.f * pz1;

        float bs0 = 3.0e38f, bs1 = 3.0e38f;
        int bi0 = 0, bi1 = 0;
#pragma unroll 8
        for (int m = 0; m < MCH; m++) {
            const float4 t = sh[m];      // warp-uniform -> smem broadcast
            float s0 = __fmaf_rn(ax0, t.x, t.w);
            s0 = __fmaf_rn(ay0, t.y, s0);
            s0 = __fmaf_rn(az0, t.z, s0);
            float s1 = __fmaf_rn(ax1, t.x, t.w);
            s1 = __fmaf_rn(ay1, t.y, s1);
            s1 = __fmaf_rn(az1, t.z, s1);
            if (s0 < bs0) { bs0 = s0; bi0 = m; }
            if (s1 < bs1) { bs1 = s1; bi1 = m; }
        }

        unsigned u0 = __float_as_uint(bs0);
        u0 = (u0 & 0x80000000u) ? ~u0 : (u0 | 0x80000000u);
        unsigned u1 = __float_as_uint(bs1);
        u1 = (u1 & 0x80000000u) ? ~u1 : (u1 | 0x80000000u);
        atomicMin(g_scr + (size_t)b * NPTS + n0,
                  ((unsigned long long)u0 << 32) | (unsigned)(mbase + bi0));
        atomicMin(g_scr + (size_t)b * NPTS + n1,
                  ((unsigned long long)u1 << 32) | (unsigned)(mbase + bi1));
        __threadfence();
    }
    __syncthreads();

    // completion count: last arriving block runs the reduce+solve tail
    if (tid == 0) {
        unsigned a = atomicAdd(&g_count, 1u);
        s_last = (a == GRID_BLKS - 1) ? 1 : 0;
    }
    __syncthreads();
    if (!s_last) return;

    __threadfence();
    critical_tail(psrc, out, step, done0);
}

// ---------------- launch ----------------
extern "C" void kernel_launch(void* const* d_in, const int* in_sizes, int n_in,
                              void* d_out, int out_size) {
    const float* psrc = (const float*)d_in[0];
    const float* ptgt = (const float*)d_in[1];
    float* out = (float*)d_out;

    init_kernel<<<(BATCH * MPTS + 255) / 256, 256>>>(ptgt);
    for (int s = 0; s < NSTEPS; s++)
        nn_step_kernel<<<GRID_BLKS, TPB>>>(psrc, out, s);
}

// round 5
// speedup vs baseline: 1.2144x; 1.2144x over previous
#include <cuda_runtime.h>
#include <math.h>

#define BATCH 2
#define NPTS 4096
#define MPTS 4096
#define NSTEPS 8
#define TOLER 1e-6f

#define TPB_A 128
#define MSPLIT 16
#define MCH (MPTS / MSPLIT)       // 256 targets per block tile
#define NCHUNK (NPTS / TPB_A)     // 32 source chunks

// ---------------- device state ----------------
__device__ float4 g_tgt4[BATCH * MPTS];             // (x,y,z,|t|^2)
__device__ unsigned long long g_scr[BATCH * NPTS];  // packed (orderable score | idx)
__device__ float g_Rcum[BATCH][9];
__device__ float g_tcum[BATCH][3];
__device__ float g_err[BATCH];
__device__ int g_done;

// ---------------- init ----------------
__global__ void init_kernel(const float* __restrict__ ptgt) {
    int i = blockIdx.x * blockDim.x + threadIdx.x;  // 0..8191
    if (i < BATCH * MPTS) {
        float x = ptgt[i * 3 + 0];
        float y = ptgt[i * 3 + 1];
        float z = ptgt[i * 3 + 2];
        g_tgt4[i] = make_float4(x, y, z, x * x + y * y + z * z);
        g_scr[i] = 0xFFFFFFFFFFFFFFFFull;
    }
    if (i == 0) g_done = 0;
    if (i < BATCH) {
        g_err[i] = 0.0f;
        float* R = g_Rcum[i];
        R[0] = 1.f; R[1] = 0.f; R[2] = 0.f;
        R[3] = 0.f; R[4] = 1.f; R[5] = 0.f;
        R[6] = 0.f; R[7] = 0.f; R[8] = 1.f;
        g_tcum[i][0] = 0.f; g_tcum[i][1] = 0.f; g_tcum[i][2] = 0.f;
    }
}

// ---------------- NN search (R2-proven inner loop; higher occupancy) ----------------
__global__ __launch_bounds__(TPB_A) void nn_kernel(const float* __restrict__ psrc) {
    __shared__ float4 sh[MCH];
    const int b = blockIdx.z;
    const int n = blockIdx.x * TPB_A + threadIdx.x;
    const int mbase = blockIdx.y * MCH;

    if (g_done) return;

    const float* Rc = g_Rcum[b];
    const float R0 = Rc[0], R1 = Rc[1], R2 = Rc[2];
    const float R3 = Rc[3], R4 = Rc[4], R5 = Rc[5];
    const float R6 = Rc[6], R7 = Rc[7], R8 = Rc[8];
    const float t0 = g_tcum[b][0], t1 = g_tcum[b][1], t2 = g_tcum[b][2];

    const float* ps = psrc + ((size_t)b * NPTS + n) * 3;
    const float x = ps[0], y = ps[1], z = ps[2];
    const float px = R0 * x + R1 * y + R2 * z + t0;
    const float py = R3 * x + R4 * y + R5 * z + t1;
    const float pz = R6 * x + R7 * y + R8 * z + t2;
    const float ax = -2.0f * px, ay = -2.0f * py, az = -2.0f * pz;

    for (int i = threadIdx.x; i < MCH; i += TPB_A)
        sh[i] = g_tgt4[b * MPTS + mbase + i];
    __syncthreads();

    float bs = 3.0e38f;
    int bi = 0;
#pragma unroll 8
    for (int m = 0; m < MCH; m++) {
        float4 t = sh[m];
        float s = __fmaf_rn(ax, t.x, t.w);
        s = __fmaf_rn(ay, t.y, s);
        s = __fmaf_rn(az, t.z, s);
        if (s < bs) { bs = s; bi = m; }
    }

    unsigned u = __float_as_uint(bs);
    u = (u & 0x80000000u) ? ~u : (u | 0x80000000u);
    unsigned long long key =
        ((unsigned long long)u << 32) | (unsigned)(mbase + bi);
    atomicMin(g_scr + (size_t)b * NPTS + n, key);
}

// ---------------- Horn quaternion Kabsch ----------------
__device__ __forceinline__ void matmul4(float* C, const float* A, const float* Bm) {
#pragma unroll
    for (int i = 0; i < 4; i++)
#pragma unroll
        for (int j = 0; j < 4; j++) {
            float a = 0.f;
#pragma unroll
            for (int k = 0; k < 4; k++) a = __fmaf_rn(A[i * 4 + k], Bm[k * 4 + j], a);
            C[i * 4 + j] = a;
        }
}

__device__ void solve_horn(const double* S, double* Rn, double* tn) {
    const double n = (double)NPTS;
    const double inv = 1.0 / n;
    const double pmx = S[0] * inv, pmy = S[1] * inv, pmz = S[2] * inv;
    const double qmx = S[3] * inv, qmy = S[4] * inv, qmz = S[5] * inv;

    const double Sxx = S[6]  - n * pmx * qmx, Sxy = S[7]  - n * pmx * qmy, Sxz = S[8]  - n * pmx * qmz;
    const double Syx = S[9]  - n * pmy * qmx, Syy = S[10] - n * pmy * qmy, Syz = S[11] - n * pmy * qmz;
    const double Szx = S[12] - n * pmz * qmx, Szy = S[13] - n * pmz * qmy, Szz = S[14] - n * pmz * qmz;

    double K[16];
    K[0]  = Sxx + Syy + Szz; K[1]  = Syz - Szy;       K[2]  = Szx - Sxz;       K[3]  = Sxy - Syx;
    K[5]  = Sxx - Syy - Szz; K[6]  = Sxy + Syx;       K[7]  = Szx + Sxz;
    K[10] = -Sxx + Syy - Szz; K[11] = Syz + Szy;
    K[15] = -Sxx - Syy + Szz;
    K[4] = K[1]; K[8] = K[2]; K[12] = K[3]; K[9] = K[6]; K[13] = K[7]; K[14] = K[11];

    double fro = 0.0;
#pragma unroll
    for (int i = 0; i < 16; i++) fro += K[i] * K[i];
    const double sc = 1.0 / sqrt(fro + 1e-300);

    float Kf[16];
#pragma unroll
    for (int i = 0; i < 16; i++) Kf[i] = (float)(K[i] * sc);
    Kf[0] += 1.f; Kf[5] += 1.f; Kf[10] += 1.f; Kf[15] += 1.f;  // eigs in [0,2]

    float K2[16], K4[16];
    matmul4(K2, Kf, Kf);
    matmul4(K4, K2, K2);

    float v0 = 1.f, v1 = 0.02f, v2 = 0.03f, v3 = 0.04f;
#pragma unroll 4
    for (int it = 0; it < 48; it++) {
        float w0 = K4[0]  * v0 + K4[1]  * v1 + K4[2]  * v2 + K4[3]  * v3;
        float w1 = K4[4]  * v0 + K4[5]  * v1 + K4[6]  * v2 + K4[7]  * v3;
        float w2 = K4[8]  * v0 + K4[9]  * v1 + K4[10] * v2 + K4[11] * v3;
        float w3 = K4[12] * v0 + K4[13] * v1 + K4[14] * v2 + K4[15] * v3;
        if ((it & 3) == 3) {
            float r = rsqrtf(w0 * w0 + w1 * w1 + w2 * w2 + w3 * w3 + 1e-30f);
            w0 *= r; w1 *= r; w2 *= r; w3 *= r;
        }
        v0 = w0; v1 = w1; v2 = w2; v3 = w3;
    }

    const double qw = v0, qx = v1, qy = v2, qz = v3;
    const double nn = qw * qw + qx * qx + qy * qy + qz * qz;
    const double s2 = 2.0 / nn;
    Rn[0] = 1.0 - s2 * (qy * qy + qz * qz); Rn[1] = s2 * (qx * qy - qw * qz); Rn[2] = s2 * (qx * qz + qw * qy);
    Rn[3] = s2 * (qx * qy + qw * qz); Rn[4] = 1.0 - s2 * (qx * qx + qz * qz); Rn[5] = s2 * (qy * qz - qw * qx);
    Rn[6] = s2 * (qx * qz - qw * qy); Rn[7] = s2 * (qy * qz + qw * qx); Rn[8] = 1.0 - s2 * (qx * qx + qy * qy);

    tn[0] = qmx - (Rn[0] * pmx + Rn[1] * pmy + Rn[2] * pmz);
    tn[1] = qmy - (Rn[3] * pmx + Rn[4] * pmy + Rn[5] * pmz);
    tn[2] = qmz - (Rn[6] * pmx + Rn[7] * pmy + Rn[8] * pmz);
}

// ---------------- tail: single block, reduce + solve + compose + re-arm ----------------
__global__ __launch_bounds__(256) void tail_kernel(const float* __restrict__ psrc,
                                                   float* __restrict__ out, int step) {
    __shared__ float cRt[BATCH][12];
    __shared__ float c_part[8][16];
    __shared__ float c_S[BATCH][16];
    __shared__ float c_errnew[BATCH];
    __shared__ int c_done;

    const int tid = threadIdx.x;
    const int done0 = g_done;

    if (tid < 24) {
        int bb = tid / 12, j = tid - bb * 12;
        cRt[bb][j] = (j < 9) ? g_Rcum[bb][j] : g_tcum[bb][j - 9];
    }
    __syncthreads();

    float acc[16];
#pragma unroll
    for (int k = 0; k < 16; k++) acc[k] = 0.f;

    const int base = tid * 32;        // 32 contiguous points; warps 0-3 b0, 4-7 b1
    const int bb = tid >> 7;

    if (!done0) {
        const float R0 = cRt[bb][0], R1 = cRt[bb][1], R2 = cRt[bb][2];
        const float R3 = cRt[bb][3], R4 = cRt[bb][4], R5 = cRt[bb][5];
        const float R6 = cRt[bb][6], R7 = cRt[bb][7], R8 = cRt[bb][8];
        const float t0 = cRt[bb][9], t1 = cRt[bb][10], t2 = cRt[bb][11];

        for (int c = 0; c < 32; c += 8) {
            unsigned long long key[8];
#pragma unroll
            for (int i = 0; i < 8; i++) key[i] = g_scr[base + c + i];
#pragma unroll
            for (int i = 0; i < 8; i++) g_scr[base + c + i] = 0xFFFFFFFFFFFFFFFFull;

            float4 q[8];
#pragma unroll
            for (int i = 0; i < 8; i++) {
                const int idx = ((int)(unsigned)(key[i] & 0xFFFFFFFFull)) & (MPTS - 1);
                q[i] = g_tgt4[(bb << 12) + idx];
            }
#pragma unroll
            for (int i = 0; i < 8; i++) {
                unsigned u = (unsigned)(key[i] >> 32);
                unsigned fb = (u & 0x80000000u) ? (u ^ 0x80000000u) : ~u;
                const float s = __uint_as_float(fb);

                const float* ps = psrc + (size_t)(base + c + i) * 3;
                const float x = ps[0], y = ps[1], z = ps[2];
                const float px = R0 * x + R1 * y + R2 * z + t0;
                const float py = R3 * x + R4 * y + R5 * z + t1;
                const float pz = R6 * x + R7 * y + R8 * z + t2;
                const float pn = px * px + py * py + pz * pz;
                const float dist = sqrtf(fmaxf(pn + s, 0.0f));

                acc[0] += px; acc[1] += py; acc[2] += pz;
                acc[3] += q[i].x; acc[4] += q[i].y; acc[5] += q[i].z;
                acc[6] += px * q[i].x; acc[7] += px * q[i].y; acc[8] += px * q[i].z;
                acc[9] += py * q[i].x; acc[10] += py * q[i].y; acc[11] += py * q[i].z;
                acc[12] += pz * q[i].x; acc[13] += pz * q[i].y; acc[14] += pz * q[i].z;
                acc[15] += dist;
            }
        }
    }

    // fixed-order deterministic reduction
#pragma unroll
    for (int k = 0; k < 16; k++) {
        float a = acc[k];
        a += __shfl_down_sync(0xffffffffu, a, 16);
        a += __shfl_down_sync(0xffffffffu, a, 8);
        a += __shfl_down_sync(0xffffffffu, a, 4);
        a += __shfl_down_sync(0xffffffffu, a, 2);
        a += __shfl_down_sync(0xffffffffu, a, 1);
        acc[k] = a;
    }
    const int lane = tid & 31, warp = tid >> 5;
    if (lane == 0) {
#pragma unroll
        for (int k = 0; k < 16; k++) c_part[warp][k] = acc[k];
    }
    __syncthreads();
    if (tid < 32) {
        const int bsel = tid >> 4, k = tid & 15;
        float a = 0.f;
#pragma unroll
        for (int w = 0; w < 4; w++) a += c_part[bsel * 4 + w][k];
        c_S[bsel][k] = a;
        if (k == 15) c_errnew[bsel] = a / (float)NPTS;
    }
    __syncthreads();

    if (tid == 0) {
        int conv = (fabsf(c_errnew[0] - g_err[0]) < TOLER) &&
                   (fabsf(c_errnew[1] - g_err[1]) < TOLER);
        c_done = (done0 || conv) ? 1 : 0;
        g_done = c_done;
    }
    __syncthreads();

    if (tid < BATCH && !c_done) {
        double S[16];
#pragma unroll
        for (int k = 0; k < 16; k++) S[k] = (double)c_S[tid][k];
        double Rn[9], tn[3];
        solve_horn(S, Rn, tn);

        double Ro[9], to[3];
#pragma unroll
        for (int i = 0; i < 9; i++) Ro[i] = (double)cRt[tid][i];
#pragma unroll
        for (int i = 0; i < 3; i++) to[i] = (double)cRt[tid][9 + i];

#pragma unroll
        for (int i = 0; i < 3; i++) {
#pragma unroll
            for (int j = 0; j < 3; j++) {
                double m = Rn[i * 3 + 0] * Ro[0 + j] + Rn[i * 3 + 1] * Ro[3 + j] +
                           Rn[i * 3 + 2] * Ro[6 + j];
                g_Rcum[tid][i * 3 + j] = (float)m;
            }
            double tm = Rn[i * 3 + 0] * to[0] + Rn[i * 3 + 1] * to[1] +
                        Rn[i * 3 + 2] * to[2] + tn[i];
            g_tcum[tid][i] = (float)tm;
        }
        g_err[tid] = c_errnew[tid];
    }
    __syncthreads();

    if (step == NSTEPS - 1 && tid < BATCH) {
        float R[9];
#pragma unroll
        for (int i = 0; i < 9; i++) R[i] = g_Rcum[tid][i];
        out[tid * 7 + 0] = g_tcum[tid][0];
        out[tid * 7 + 1] = g_tcum[tid][1];
        out[tid * 7 + 2] = g_tcum[tid][2];
        const float r00 = R[0], r11 = R[4], r22 = R[8];
        float qw = 0.5f * sqrtf(fmaxf(1.f + r00 + r11 + r22, 1e-12f));
        float qx = 0.5f * sqrtf(fmaxf(1.f + r00 - r11 - r22, 1e-12f));
        float qy = 0.5f * sqrtf(fmaxf(1.f - r00 + r11 - r22, 1e-12f));
        float qz = 0.5f * sqrtf(fmaxf(1.f - r00 - r11 + r22, 1e-12f));
        qx = (R[7] - R[5] >= 0.f) ? qx : -qx;
        qy = (R[2] - R[6] >= 0.f) ? qy : -qy;
        qz = (R[3] - R[1] >= 0.f) ? qz : -qz;
        out[tid * 7 + 3] = qx;
        out[tid * 7 + 4] = qy;
        out[tid * 7 + 5] = qz;
        out[tid * 7 + 6] = qw;
    }
}

// ---------------- launch ----------------
extern "C" void kernel_launch(void* const* d_in, const int* in_sizes, int n_in,
                              void* d_out, int out_size) {
    const float* psrc = (const float*)d_in[0];
    const float* ptgt = (const float*)d_in[1];
    float* out = (float*)d_out;

    init_kernel<<<(BATCH * MPTS + 255) / 256, 256>>>(ptgt);

    for (int s = 0; s < NSTEPS; s++) {
        dim3 gA(NCHUNK, MSPLIT, BATCH);
        nn_kernel<<<gA, TPB_A>>>(psrc);
        tail_kernel<<<1, 256>>>(psrc, out, s);
    }
}